// round 1
// baseline (speedup 1.0000x reference)
#include <cuda_runtime.h>

#define FRAME   160
#define ORDER   16
#define EPS     1e-8f
#define CH      20          // samples per lane
#define LPF     8           // lanes per frame
#define FPW     4           // frames per warp
#define WARPS   8
#define THREADS (WARPS * 32)
#define FSTRIDE 193         // shared floats per frame region: 16 pad + 160 + 16 pad + 1
#define WSTRIDE (FPW * FSTRIDE)

__global__ __launch_bounds__(THREADS)
void lpc_residual_kernel(const float* __restrict__ x,
                         float* __restrict__ out,
                         int nframes)
{
    __shared__ float sx[WARPS * WSTRIDE];

    const int lane = threadIdx.x & 31;
    const int wid  = threadIdx.x >> 5;
    const int warpGlobal = blockIdx.x * WARPS + wid;
    const int frame0 = warpGlobal * FPW;

    float* sw = sx + wid * WSTRIDE;

    // ---- zero the pad cells: per frame, cells [0,16) and [176,193) ----
    #pragma unroll
    for (int j = lane; j < FPW * 33; j += 32) {
        int f = j / 33;
        int c = j % 33;
        int cell = (c < 16) ? c : (c + 160);
        sw[f * FSTRIDE + cell] = 0.0f;
    }

    // ---- stage input: coalesced global -> shared (160 = 32*5, so each t is one frame) ----
    const float* gx = x + (long long)frame0 * FRAME;
    #pragma unroll
    for (int t = 0; t < 20; t++) {
        int f = t / 5;
        int rr = (t % 5) * 32 + lane;
        if (frame0 + f < nframes)
            sw[f * FSTRIDE + 16 + rr] = gx[f * FRAME + rr];
    }
    __syncwarp();

    const int fl = lane >> 3;   // frame within warp (0..3)
    const int p  = lane & 7;    // sub-lane within frame (0..7)
    // base points at logical sample x[20p] of this frame (pads live at negative / >=160 idx)
    const float* base = sw + fl * FSTRIDE + 16 + p * CH;

    // ---- autocorrelation window: x[20p .. 20p+35] (tail reads hit zero pad) ----
    float w[CH + ORDER];
    #pragma unroll
    for (int c = 0; c < CH + ORDER; c++) w[c] = base[c];

    float r[ORDER + 1];
    #pragma unroll
    for (int k = 0; k <= ORDER; k++) {
        float acc = 0.0f;
        #pragma unroll
        for (int m = 0; m < CH; m++)
            acc = fmaf(w[m], w[m + k], acc);
        // reduce across the 8 lanes of this frame; result lands in all 8 lanes
        acc += __shfl_xor_sync(0xFFFFFFFFu, acc, 1);
        acc += __shfl_xor_sync(0xFFFFFFFFu, acc, 2);
        acc += __shfl_xor_sync(0xFFFFFFFFu, acc, 4);
        r[k] = acc;
    }

    // ---- Levinson-Durbin, fully unrolled (all indices compile-time -> registers) ----
    float a[ORDER + 1];
    a[0] = 1.0f;
    float e = (r[0] != 0.0f) ? r[0] : EPS;
    #pragma unroll
    for (int i = 1; i <= ORDER; i++) {
        float acc = r[i];
        #pragma unroll
        for (int j = 1; j < i; j++)
            acc -= a[j] * r[i - j];
        float kk = acc / e;
        float tnew[ORDER + 1];
        #pragma unroll
        for (int j = 1; j < i; j++)
            tnew[j] = a[j] - kk * a[i - j];
        #pragma unroll
        for (int j = 1; j < i; j++)
            a[j] = tnew[j];
        a[i] = kk;
        e = fmaxf(e * (1.0f - kk * kk), EPS);
    }

    // ---- FIR: res[n] = sum_k a[k] * x[n-k]  (zero pad handles n-k < 0) ----
    // window needed: x[20p-16 .. 20p+19]  -> v[c] = base[c-16], c in [0,36)
    float v[CH + ORDER];
    #pragma unroll
    for (int c = 0; c < CH + ORDER; c++) v[c] = base[c - 16];

    float res[CH];
    #pragma unroll
    for (int m = 0; m < CH; m++) {
        float s = v[ORDER + m];            // a[0] = 1
        #pragma unroll
        for (int k = 1; k <= ORDER; k++)
            s = fmaf(a[k], v[ORDER + m - k], s);
        res[m] = s;
    }

    // ---- stage output through shared for coalesced stores ----
    __syncwarp();   // all lanes done reading staged input
    {
        float* bw = sw + fl * FSTRIDE + 16 + p * CH;
        #pragma unroll
        for (int m = 0; m < CH; m++)
            bw[m] = res[m];
    }
    __syncwarp();

    float* go = out + (long long)frame0 * FRAME;
    #pragma unroll
    for (int t = 0; t < 20; t++) {
        int f = t / 5;
        int rr = (t % 5) * 32 + lane;
        if (frame0 + f < nframes)
            go[f * FRAME + rr] = sw[f * FSTRIDE + 16 + rr];
    }
}

extern "C" void kernel_launch(void* const* d_in, const int* in_sizes, int n_in,
                              void* d_out, int out_size)
{
    const float* x = (const float*)d_in[0];
    float* out = (float*)d_out;

    long long total = in_sizes[0];
    int nframes = (int)(total / FRAME);           // 128000 for the given shape
    int warpsNeeded = (nframes + FPW - 1) / FPW;
    int blocks = (warpsNeeded + WARPS - 1) / WARPS;

    lpc_residual_kernel<<<blocks, THREADS>>>(x, out, nframes);
}